// round 7
// baseline (speedup 1.0000x reference)
#include <cuda_runtime.h>
#include <cuda_bf16.h>
#include <cstdint>
#include <math.h>

// ---------------------------------------------------------------------------
// RND bonus + normalization. Split-bf16 (emulated fp32) warp-MMA kernel.
// (tcgen05 is unavailable: harness compiles via virtual arch compute_103,
//  which gates all sm_103a-suffix PTX. mma.sync + ldmatrix + cp.async only.)
// ---------------------------------------------------------------------------

#define BATCH_N 524288
#define NTILES  4096         // 524288 / 128

// SMEM layout (bytes). Tile bases 1024-aligned for SW128 swizzle.
#define OFF_BIAS 0           // 5 slots x 512B: tb1, tb2, pb1, pb2, (tb3-pb3)
#define OFF_OBS  3072        // obs hi 16K @ +0, lo 16K @ +16384
#define OFF_ACT  35840       // act hi 32K @ +0, lo 32K @ +32768
#define OFF_W0   101376      // weight buffer 0 (64K)
#define OFF_W1   166912      // weight buffer 1 (64K)
#define SMEM_BYTES 232448    // == 227 KB max dynamic smem per block

__device__ __align__(256) unsigned char g_wimg[327680];
__device__ double g_acc[2];
__device__ float  g_stats[2];

// ------------------------------- helpers -----------------------------------
#define SWZ128(off) ((off) ^ (((off) >> 3) & 0x70))

__device__ __forceinline__ uint32_t off64(int r, int k) {        // 64-wide K tile (128B rows)
    return (uint32_t)(r * 128 + k * 2);
}
__device__ __forceinline__ uint32_t aoff128(int r, int k) {      // 128-wide: blocked SW128 atoms
    return (uint32_t)((((r >> 3) + ((k >> 6) << 4)) << 10) + ((r & 7) << 7) + ((k & 63) << 1));
}

__device__ __forceinline__ uint32_t smem_u32(const void* p) {
    uint32_t a;
    asm("{ .reg .u64 t; cvta.to.shared.u64 t, %1; cvt.u32.u64 %0, t; }" : "=r"(a) : "l"(p));
    return a;
}

__device__ __forceinline__ void ldsm4(uint32_t r[4], uint32_t addr) {
    asm volatile("ldmatrix.sync.aligned.m8n8.x4.shared.b16 {%0,%1,%2,%3}, [%4];"
                 : "=r"(r[0]), "=r"(r[1]), "=r"(r[2]), "=r"(r[3]) : "r"(addr));
}

__device__ __forceinline__ void mma16816(float c[4], const uint32_t a[4], const uint32_t b[2]) {
    asm volatile("mma.sync.aligned.m16n8k16.row.col.f32.bf16.bf16.f32 "
                 "{%0,%1,%2,%3}, {%4,%5,%6,%7}, {%8,%9}, {%0,%1,%2,%3};"
                 : "+f"(c[0]), "+f"(c[1]), "+f"(c[2]), "+f"(c[3])
                 : "r"(a[0]), "r"(a[1]), "r"(a[2]), "r"(a[3]), "r"(b[0]), "r"(b[1]));
}

__device__ __forceinline__ void cp_w(const unsigned char* g, uint32_t sdst, int bytes, int tid) {
    #pragma unroll 4
    for (int i = tid * 16; i < bytes; i += 256 * 16) {
        asm volatile("cp.async.cg.shared.global [%0], [%1], 16;" :: "r"(sdst + i), "l"(g + i));
    }
    asm volatile("cp.async.commit_group;" ::: "memory");
}
#define CP_WAIT() asm volatile("cp.async.wait_group 0;" ::: "memory")

__device__ __forceinline__ uint32_t pack_split(float x0, float x1, uint32_t& lo) {
    __nv_bfloat16 h0 = __float2bfloat16(x0), h1 = __float2bfloat16(x1);
    __nv_bfloat16 l0 = __float2bfloat16(x0 - __bfloat162float(h0));
    __nv_bfloat16 l1 = __float2bfloat16(x1 - __bfloat162float(h1));
    __nv_bfloat162 H = __halves2bfloat162(h0, h1), L = __halves2bfloat162(l0, l1);
    lo = *reinterpret_cast<uint32_t*>(&L);
    return *reinterpret_cast<uint32_t*>(&H);
}

// ---------------------------------------------------------------------------
// Prep: split fp32 weights into swizzled bf16 hi/lo images; zero accumulators.
// ---------------------------------------------------------------------------
__global__ void rnd_prep(const float* W0, const float* W1, const float* W2,
                         const float* W3, const float* W4, const float* W5) {
    int L = blockIdx.y;
    if (L == 0 && blockIdx.x == 0 && threadIdx.x == 0) { g_acc[0] = 0.0; g_acc[1] = 0.0; }
    const float* W = (L == 0) ? W0 : (L == 1) ? W1 : (L == 2) ? W2
                   : (L == 3) ? W3 : (L == 4) ? W4 : W5;
    int K = ((L % 3) == 0) ? 64 : 128;
    int idx = blockIdx.x * blockDim.x + threadIdx.x;
    if (idx >= 128 * K) return;
    int n = idx / K, k = idx % K;
    float w = W[idx];
    __nv_bfloat16 h = __float2bfloat16(w);
    __nv_bfloat16 l = __float2bfloat16(w - __bfloat162float(h));
    uint32_t off = (K == 64) ? off64(n, k) : aoff128(n, k);
    uint32_t sw = SWZ128(off);
    int hsz = (K == 64) ? 16384 : 32768;
    const int loff[6] = {0, 32768, 98304, 163840, 196608, 262144};
    unsigned char* base = g_wimg + loff[L];
    *reinterpret_cast<__nv_bfloat16*>(base + sw) = h;
    *reinterpret_cast<__nv_bfloat16*>(base + hsz + sw) = l;
}

// ---------------------------------------------------------------------------
// One GEMM layer: acc[128x128-tile slice] += A(hi+lo) @ W(hi+lo)^T, 3 terms.
// Each warp: 64x32 output. All fragments loaded once per k-step.
// ---------------------------------------------------------------------------
template <int K>
__device__ __forceinline__ void gemm_layer(uint32_t sb, uint32_t aBase, uint32_t aLo,
                                           uint32_t wBase, uint32_t wLo,
                                           float acc[4][4][4], int lane, int mwarp, int nwarp) {
    const int r_l = lane & 15;
    const int k_l = (lane >> 4) * 8;
    #pragma unroll 1
    for (int kk = 0; kk < K; kk += 16) {
        uint32_t Ah[4][4], Al[4][4], Bh[4][2], Bl[4][2];
        #pragma unroll
        for (int mt = 0; mt < 4; mt++) {
            int row = mwarp * 64 + mt * 16 + r_l;
            uint32_t off = (K == 128) ? aoff128(row, kk + k_l) : off64(row, kk + k_l);
            uint32_t ad = sb + aBase + SWZ128(off);
            ldsm4(Ah[mt], ad);
            ldsm4(Al[mt], ad + aLo);
        }
        #pragma unroll
        for (int p = 0; p < 2; p++) {
            int n = nwarp * 32 + p * 16 + r_l;
            uint32_t off = (K == 128) ? aoff128(n, kk + k_l) : off64(n, kk + k_l);
            uint32_t wd = sb + wBase + SWZ128(off);
            uint32_t q[4];
            ldsm4(q, wd);
            Bh[p * 2][0] = q[0]; Bh[p * 2][1] = q[2];
            Bh[p * 2 + 1][0] = q[1]; Bh[p * 2 + 1][1] = q[3];
            ldsm4(q, wd + wLo);
            Bl[p * 2][0] = q[0]; Bl[p * 2][1] = q[2];
            Bl[p * 2 + 1][0] = q[1]; Bl[p * 2 + 1][1] = q[3];
        }
        #pragma unroll
        for (int mt = 0; mt < 4; mt++)
            #pragma unroll
            for (int nt = 0; nt < 4; nt++) {
                mma16816(acc[mt][nt], Ah[mt], Bh[nt]);
                mma16816(acc[mt][nt], Al[mt], Bh[nt]);
                mma16816(acc[mt][nt], Ah[mt], Bl[nt]);
            }
    }
}

__device__ __forceinline__ void zero_acc(float acc[4][4][4]) {
    #pragma unroll
    for (int i = 0; i < 4; i++)
        #pragma unroll
        for (int j = 0; j < 4; j++)
            #pragma unroll
            for (int q = 0; q < 4; q++) acc[i][j][q] = 0.f;
}

// bias + relu + hi/lo split + swizzled store into act buffer
__device__ __forceinline__ void epi(char* smem, int bslot, float acc[4][4][4],
                                    int lane, int mwarp, int nwarp) {
    const float* bias = reinterpret_cast<const float*>(smem + OFF_BIAS + bslot * 512);
    int g = lane >> 2, tig = lane & 3;
    #pragma unroll
    for (int mt = 0; mt < 4; mt++)
        #pragma unroll
        for (int nt = 0; nt < 4; nt++) {
            int col = nwarp * 32 + nt * 8 + tig * 2;
            float b0 = bias[col], b1 = bias[col + 1];
            #pragma unroll
            for (int h = 0; h < 2; h++) {
                int row = mwarp * 64 + mt * 16 + g + h * 8;
                float x0 = fmaxf(acc[mt][nt][h * 2] + b0, 0.f);
                float x1 = fmaxf(acc[mt][nt][h * 2 + 1] + b1, 0.f);
                uint32_t lo, hi = pack_split(x0, x1, lo);
                uint32_t off = SWZ128(aoff128(row, col));
                *reinterpret_cast<uint32_t*>(smem + OFF_ACT + off) = hi;
                *reinterpret_cast<uint32_t*>(smem + OFF_ACT + 32768 + off) = lo;
            }
        }
}

// ---------------------------------------------------------------------------
// Main fused kernel: 1 CTA = 128 rows, 8 warps (2m x 4n), 6 GEMMs.
// ---------------------------------------------------------------------------
__global__ void __launch_bounds__(256, 1) rnd_main(
    const float* __restrict__ obs, float* __restrict__ out,
    const float* __restrict__ tb1, const float* __restrict__ tb2,
    const float* __restrict__ tb3, const float* __restrict__ pb1,
    const float* __restrict__ pb2, const float* __restrict__ pb3) {
    extern __shared__ char smem[];
    uint32_t sb = smem_u32(smem);
    int tid = threadIdx.x, lane = tid & 31, wid = tid >> 5;
    int mwarp = wid >> 2, nwarp = wid & 3;
    int tile = blockIdx.x;

    // biases (slots: tb1, tb2, pb1, pb2, tb3-pb3)
    for (int i = tid; i < 640; i += 256) {
        int slot = i >> 7, j = i & 127; float v;
        if (slot == 0) v = tb1[j];
        else if (slot == 1) v = tb2[j];
        else if (slot == 2) v = pb1[j];
        else if (slot == 3) v = pb2[j];
        else v = tb3[j] - pb3[j];
        *reinterpret_cast<float*>(smem + OFF_BIAS + i * 4) = v;
    }

    // prefetch t1 weights
    cp_w(g_wimg + 0, sb + OFF_W0, 32768, tid);

    // obs tile -> bf16 hi/lo, SW128 (64 cols = 128B rows)
    const float4* o4 = reinterpret_cast<const float4*>(obs + (size_t)tile * (128 * 64));
    #pragma unroll
    for (int i = 0; i < 8; i++) {
        int idx = i * 256 + tid;
        float4 v = o4[idx];
        int row = idx >> 4, f4 = idx & 15;
        uint32_t lo0, hi0 = pack_split(v.x, v.y, lo0);
        uint32_t lo1, hi1 = pack_split(v.z, v.w, lo1);
        uint32_t sw = SWZ128((uint32_t)(row * 128 + f4 * 8));
        *reinterpret_cast<uint2*>(smem + OFF_OBS + sw) = make_uint2(hi0, hi1);
        *reinterpret_cast<uint2*>(smem + OFF_OBS + 16384 + sw) = make_uint2(lo0, lo1);
    }
    CP_WAIT();
    __syncthreads();

    float acc[4][4][4], tk[4][4][4];

    // ---- L0: t1 = relu(obs @ tW1 + tb1) ----
    zero_acc(acc);
    cp_w(g_wimg + 32768, sb + OFF_W1, 65536, tid);                 // prefetch tW2
    gemm_layer<64>(sb, OFF_OBS, 16384, OFF_W0, 16384, acc, lane, mwarp, nwarp);
    __syncthreads();
    epi(smem, 0, acc, lane, mwarp, nwarp);
    CP_WAIT(); __syncthreads();

    // ---- L1: t2 ----
    zero_acc(acc);
    cp_w(g_wimg + 98304, sb + OFF_W0, 65536, tid);                 // prefetch tW3
    gemm_layer<128>(sb, OFF_ACT, 32768, OFF_W1, 32768, acc, lane, mwarp, nwarp);
    __syncthreads();
    epi(smem, 1, acc, lane, mwarp, nwarp);
    CP_WAIT(); __syncthreads();

    // ---- L2: t3 -> kept in registers (tk) ----
    zero_acc(tk);
    cp_w(g_wimg + 163840, sb + OFF_W1, 32768, tid);                // prefetch pW1
    gemm_layer<128>(sb, OFF_ACT, 32768, OFF_W0, 32768, tk, lane, mwarp, nwarp);
    __syncthreads();
    CP_WAIT(); __syncthreads();

    // ---- L3: p1 ----
    zero_acc(acc);
    cp_w(g_wimg + 196608, sb + OFF_W0, 65536, tid);                // prefetch pW2
    gemm_layer<64>(sb, OFF_OBS, 16384, OFF_W1, 16384, acc, lane, mwarp, nwarp);
    __syncthreads();
    epi(smem, 2, acc, lane, mwarp, nwarp);
    CP_WAIT(); __syncthreads();

    // ---- L4: p2 ----
    zero_acc(acc);
    cp_w(g_wimg + 262144, sb + OFF_W1, 65536, tid);                // prefetch pW3
    gemm_layer<128>(sb, OFF_ACT, 32768, OFF_W0, 32768, acc, lane, mwarp, nwarp);
    __syncthreads();
    epi(smem, 3, acc, lane, mwarp, nwarp);
    CP_WAIT(); __syncthreads();

    // ---- L5: p3 ----
    zero_acc(acc);
    gemm_layer<128>(sb, OFF_ACT, 32768, OFF_W1, 32768, acc, lane, mwarp, nwarp);
    __syncthreads();

    // ---- rewards: mean((t3 - p3 + (tb3-pb3))^2) per row ----
    {
        const float* db = reinterpret_cast<const float*>(smem + OFF_BIAS + 4 * 512);
        int g = lane >> 2, tig = lane & 3;
        float rs[8];
        #pragma unroll
        for (int i = 0; i < 8; i++) rs[i] = 0.f;
        #pragma unroll
        for (int mt = 0; mt < 4; mt++)
            #pragma unroll
            for (int nt = 0; nt < 4; nt++) {
                int col = nwarp * 32 + nt * 8 + tig * 2;
                float b0 = db[col], b1 = db[col + 1];
                #pragma unroll
                for (int h = 0; h < 2; h++) {
                    float d0 = tk[mt][nt][h * 2]     - acc[mt][nt][h * 2]     + b0;
                    float d1 = tk[mt][nt][h * 2 + 1] - acc[mt][nt][h * 2 + 1] + b1;
                    rs[mt * 2 + h] = fmaf(d0, d0, fmaf(d1, d1, rs[mt * 2 + h]));
                }
            }
        #pragma unroll
        for (int i = 0; i < 8; i++) {
            rs[i] += __shfl_xor_sync(0xffffffffu, rs[i], 1);
            rs[i] += __shfl_xor_sync(0xffffffffu, rs[i], 2);
        }
        float* part = reinterpret_cast<float*>(smem + OFF_ACT);
        if (tig == 0) {
            #pragma unroll
            for (int i = 0; i < 8; i++) {
                int mt = i >> 1, h = i & 1;
                int row = mwarp * 64 + mt * 16 + g + h * 8;
                part[nwarp * 128 + row] = rs[i];
            }
        }
    }
    __syncthreads();
    if (tid < 128) {
        const float* part = reinterpret_cast<const float*>(smem + OFF_ACT);
        float r = (part[tid] + part[128 + tid] + part[256 + tid] + part[384 + tid]) * (1.0f / 128.0f);
        out[(size_t)tile * 128 + tid] = r;
        double s = (double)r, q = (double)r * (double)r;
        #pragma unroll
        for (int o = 16; o; o >>= 1) {
            s += __shfl_down_sync(0xffffffffu, s, o);
            q += __shfl_down_sync(0xffffffffu, q, o);
        }
        if (lane == 0) {
            reinterpret_cast<double*>(smem + OFF_ACT + 2048)[wid] = s;
            reinterpret_cast<double*>(smem + OFF_ACT + 2048)[4 + wid] = q;
        }
    }
    __syncthreads();
    if (tid == 0) {
        const double* d = reinterpret_cast<const double*>(smem + OFF_ACT + 2048);
        atomicAdd(&g_acc[0], d[0] + d[1] + d[2] + d[3]);
        atomicAdd(&g_acc[1], d[4] + d[5] + d[6] + d[7]);
    }
}

// ---------------------------------------------------------------------------
// Finalize (Chan merge with running stats) + normalize
// ---------------------------------------------------------------------------
__global__ void rnd_finalize(const float* rm, const float* rm2, const float* rc) {
    double n = (double)BATCH_N;
    double sum = g_acc[0], sq = g_acc[1];
    double bmean = sum / n;
    double bm2 = sq - sum * sum / n;
    double c0 = (double)rc[0];
    double nc = c0 + n;
    double delta = bmean - (double)rm[0];
    double nmean = (double)rm[0] + delta * n / nc;
    double nm2 = (double)rm2[0] + bm2 + delta * delta * c0 * n / nc;
    float stdv = (nc > 1.0) ? (float)sqrt(nm2 / (nc - 1.0)) : 1.0f;
    g_stats[0] = (float)nmean;
    g_stats[1] = 1.0f / (stdv + 1e-8f);
}

__global__ void rnd_norm(float* out) {
    float m = g_stats[0], inv = g_stats[1];
    int i = blockIdx.x * blockDim.x + threadIdx.x;
    if (i < BATCH_N) out[i] = (out[i] - m) * inv;
}

// ---------------------------------------------------------------------------
extern "C" void kernel_launch(void* const* d_in, const int* in_sizes, int n_in,
                              void* d_out, int out_size) {
    const float* obs = (const float*)d_in[0];
    const float* rm  = (const float*)d_in[1];
    const float* rm2 = (const float*)d_in[2];
    const float* rc  = (const float*)d_in[3];
    const float* tW1 = (const float*)d_in[4];
    const float* tb1 = (const float*)d_in[5];
    const float* tW2 = (const float*)d_in[6];
    const float* tb2 = (const float*)d_in[7];
    const float* tW3 = (const float*)d_in[8];
    const float* tb3 = (const float*)d_in[9];
    const float* pW1 = (const float*)d_in[10];
    const float* pb1 = (const float*)d_in[11];
    const float* pW2 = (const float*)d_in[12];
    const float* pb2 = (const float*)d_in[13];
    const float* pW3 = (const float*)d_in[14];
    const float* pb3 = (const float*)d_in[15];
    float* out = (float*)d_out;

    cudaFuncSetAttribute(rnd_main, cudaFuncAttributeMaxDynamicSharedMemorySize, SMEM_BYTES);

    rnd_prep<<<dim3(64, 6), 256>>>(tW1, tW2, tW3, pW1, pW2, pW3);
    rnd_main<<<NTILES, 256, SMEM_BYTES>>>(obs, out, tb1, tb2, tb3, pb1, pb2, pb3);
    rnd_finalize<<<1, 1>>>(rm, rm2, rc);
    rnd_norm<<<(BATCH_N + 255) / 256, 256>>>(out);
}

// round 12
// speedup vs baseline: 1.3535x; 1.3535x over previous
#include <cuda_runtime.h>
#include <cuda_bf16.h>
#include <cstdint>
#include <math.h>

// ---------------------------------------------------------------------------
// RND bonus + normalization. Single-pass TF32 warp-MMA kernel (mma.sync
// m16n8k8.tf32, cvt.rna everywhere). tcgen05 unavailable (virtual arch
// compute_103 gates sm_103a-suffixed PTX).
// ---------------------------------------------------------------------------

#define BATCH_N 524288
#define NTILES  4096         // 524288 / 128

// SMEM layout (bytes)
#define OFF_BIAS 0           // 5 slots x 512B: tb1, tb2, pb1, pb2, (tb3-pb3)
#define OFF_OBS  3072        // obs tf32: 128 x 64 x 4 = 32K
#define OFF_ACT  35840       // act tf32: 128 x 128 x 4 = 64K
#define OFF_W0   101376      // weight buffer 0 (64K)
#define OFF_W1   166912      // weight buffer 1 (64K)
#define SMEM_BYTES 232448    // == 227 KB limit

__device__ __align__(256) unsigned char g_wimg[327680];
__device__ double g_acc[2];
__device__ float  g_stats[2];

// ------------------------------- helpers -----------------------------------
// 32-bit-element XOR swizzle: row-major, C cols, 16B chunks XORed by row&7.
__device__ __forceinline__ uint32_t s32off(int r, int c, int C) {
    return (uint32_t)(r * C * 4 + ((((c >> 2) ^ (r & 7))) << 4) + ((c & 3) << 2));
}

__device__ __forceinline__ uint32_t smem_u32(const void* p) {
    uint32_t a;
    asm("{ .reg .u64 t; cvta.to.shared.u64 t, %1; cvt.u32.u64 %0, t; }" : "=r"(a) : "l"(p));
    return a;
}

__device__ __forceinline__ uint32_t f2tf32(float x) {
    uint32_t r;
    asm("cvt.rna.tf32.f32 %0, %1;" : "=r"(r) : "f"(x));
    return r;
}

__device__ __forceinline__ void ldsm4(uint32_t r[4], uint32_t addr) {
    asm volatile("ldmatrix.sync.aligned.m8n8.x4.shared.b16 {%0,%1,%2,%3}, [%4];"
                 : "=r"(r[0]), "=r"(r[1]), "=r"(r[2]), "=r"(r[3]) : "r"(addr));
}

__device__ __forceinline__ void mma_tf32(float c[4], const uint32_t a[4], const uint32_t b[2]) {
    asm volatile("mma.sync.aligned.m16n8k8.row.col.f32.tf32.tf32.f32 "
                 "{%0,%1,%2,%3}, {%4,%5,%6,%7}, {%8,%9}, {%0,%1,%2,%3};"
                 : "+f"(c[0]), "+f"(c[1]), "+f"(c[2]), "+f"(c[3])
                 : "r"(a[0]), "r"(a[1]), "r"(a[2]), "r"(a[3]), "r"(b[0]), "r"(b[1]));
}

__device__ __forceinline__ void cp_w(const unsigned char* g, uint32_t sdst, int bytes, int tid) {
    #pragma unroll 4
    for (int i = tid * 16; i < bytes; i += 256 * 16) {
        asm volatile("cp.async.cg.shared.global [%0], [%1], 16;" :: "r"(sdst + i), "l"(g + i));
    }
    asm volatile("cp.async.commit_group;" ::: "memory");
}
#define CP_WAIT() asm volatile("cp.async.wait_group 0;" ::: "memory")

// ---------------------------------------------------------------------------
// Prep: convert fp32 weights to tf32 (rna) into swizzled images; zero acc.
// ---------------------------------------------------------------------------
__global__ void rnd_prep(const float* W0, const float* W1, const float* W2,
                         const float* W3, const float* W4, const float* W5) {
    int L = blockIdx.y;
    if (L == 0 && blockIdx.x == 0 && threadIdx.x == 0) { g_acc[0] = 0.0; g_acc[1] = 0.0; }
    const float* W = (L == 0) ? W0 : (L == 1) ? W1 : (L == 2) ? W2
                   : (L == 3) ? W3 : (L == 4) ? W4 : W5;
    int K = ((L % 3) == 0) ? 64 : 128;
    int idx = blockIdx.x * blockDim.x + threadIdx.x;
    if (idx >= 128 * K) return;
    int n = idx / K, k = idx % K;
    const int loff[6] = {0, 32768, 98304, 163840, 196608, 262144};
    unsigned char* base = g_wimg + loff[L];
    *reinterpret_cast<uint32_t*>(base + s32off(n, k, K)) = f2tf32(W[idx]);
}

// ---------------------------------------------------------------------------
// One GEMM layer: acc[warp 64x32 slice] += A @ W^T (tf32 single-pass).
// ---------------------------------------------------------------------------
template <int C>
__device__ __forceinline__ void gemm_layer(uint32_t sb, uint32_t aBase, uint32_t wBase,
                                           float acc[4][4][4], int lane, int mwarp, int nwarp) {
    const int rowin = lane & 7;
    const int tile = lane >> 3;
    const int rsel = (tile & 1) * 8 + rowin;   // row within 16-row group
    const int csel = tile >> 1;                // k-chunk offset (0/1)
    #pragma unroll 4
    for (int kk = 0; kk < C; kk += 8) {
        int chunk = (kk >> 2) + csel;
        uint32_t Af[4][4], Bf[4][2];
        #pragma unroll
        for (int mt = 0; mt < 4; mt++) {
            int row = mwarp * 64 + mt * 16 + rsel;
            uint32_t addr = sb + aBase + (uint32_t)(row * C * 4 + (((chunk ^ (row & 7))) << 4));
            ldsm4(Af[mt], addr);
        }
        #pragma unroll
        for (int p = 0; p < 2; p++) {
            int n = nwarp * 32 + p * 16 + rsel;
            uint32_t addr = sb + wBase + (uint32_t)(n * C * 4 + (((chunk ^ (n & 7))) << 4));
            uint32_t q[4];
            ldsm4(q, addr);
            Bf[p * 2][0] = q[0]; Bf[p * 2][1] = q[2];
            Bf[p * 2 + 1][0] = q[1]; Bf[p * 2 + 1][1] = q[3];
        }
        #pragma unroll
        for (int mt = 0; mt < 4; mt++)
            #pragma unroll
            for (int nt = 0; nt < 4; nt++)
                mma_tf32(acc[mt][nt], Af[mt], Bf[nt]);
    }
}

__device__ __forceinline__ void zero_acc(float acc[4][4][4]) {
    #pragma unroll
    for (int i = 0; i < 4; i++)
        #pragma unroll
        for (int j = 0; j < 4; j++)
            #pragma unroll
            for (int q = 0; q < 4; q++) acc[i][j][q] = 0.f;
}

// bias + relu + tf32-round + swizzled store into act buffer (C=128)
__device__ __forceinline__ void epi(char* smem, int bslot, float acc[4][4][4],
                                    int lane, int mwarp, int nwarp) {
    const float* bias = reinterpret_cast<const float*>(smem + OFF_BIAS + bslot * 512);
    int g = lane >> 2, tig = lane & 3;
    #pragma unroll
    for (int mt = 0; mt < 4; mt++)
        #pragma unroll
        for (int nt = 0; nt < 4; nt++) {
            int col = nwarp * 32 + nt * 8 + tig * 2;
            float b0 = bias[col], b1 = bias[col + 1];
            #pragma unroll
            for (int h = 0; h < 2; h++) {
                int row = mwarp * 64 + mt * 16 + g + h * 8;
                uint32_t x0 = f2tf32(fmaxf(acc[mt][nt][h * 2]     + b0, 0.f));
                uint32_t x1 = f2tf32(fmaxf(acc[mt][nt][h * 2 + 1] + b1, 0.f));
                *reinterpret_cast<uint2*>(smem + OFF_ACT + s32off(row, col, 128)) =
                    make_uint2(x0, x1);
            }
        }
}

// ---------------------------------------------------------------------------
// Main fused kernel: 1 CTA = 128 rows, 8 warps (2m x 4n), 6 GEMMs.
// ---------------------------------------------------------------------------
__global__ void __launch_bounds__(256, 1) rnd_main(
    const float* __restrict__ obs, float* __restrict__ out,
    const float* __restrict__ tb1, const float* __restrict__ tb2,
    const float* __restrict__ tb3, const float* __restrict__ pb1,
    const float* __restrict__ pb2, const float* __restrict__ pb3) {
    extern __shared__ char smem[];
    uint32_t sb = smem_u32(smem);
    int tid = threadIdx.x, lane = tid & 31, wid = tid >> 5;
    int mwarp = wid >> 2, nwarp = wid & 3;
    int tile = blockIdx.x;

    // biases (slots: tb1, tb2, pb1, pb2, tb3-pb3)
    for (int i = tid; i < 640; i += 256) {
        int slot = i >> 7, j = i & 127; float v;
        if (slot == 0) v = tb1[j];
        else if (slot == 1) v = tb2[j];
        else if (slot == 2) v = pb1[j];
        else if (slot == 3) v = pb2[j];
        else v = tb3[j] - pb3[j];
        *reinterpret_cast<float*>(smem + OFF_BIAS + i * 4) = v;
    }

    // prefetch t1 weights
    cp_w(g_wimg + 0, sb + OFF_W0, 32768, tid);

    // obs tile -> tf32, swizzled (C=64). Each iter: one 16B chunk per thread.
    const float4* o4 = reinterpret_cast<const float4*>(obs + (size_t)tile * (128 * 64));
    #pragma unroll
    for (int i = 0; i < 8; i++) {
        int idx = i * 256 + tid;
        float4 v = o4[idx];
        int row = idx >> 4, c4 = idx & 15;
        uint32_t addr = OFF_OBS + (uint32_t)(row * 256 + ((c4 ^ (row & 7)) << 4));
        *reinterpret_cast<uint4*>(smem + addr) =
            make_uint4(f2tf32(v.x), f2tf32(v.y), f2tf32(v.z), f2tf32(v.w));
    }
    CP_WAIT();
    __syncthreads();

    float acc[4][4][4], tk[4][4][4];

    // ---- L0: t1 = relu(obs @ tW1 + tb1) ----
    zero_acc(acc);
    cp_w(g_wimg + 32768, sb + OFF_W1, 65536, tid);                 // prefetch tW2
    gemm_layer<64>(sb, OFF_OBS, OFF_W0, acc, lane, mwarp, nwarp);
    __syncthreads();
    epi(smem, 0, acc, lane, mwarp, nwarp);
    CP_WAIT(); __syncthreads();

    // ---- L1: t2 ----
    zero_acc(acc);
    cp_w(g_wimg + 98304, sb + OFF_W0, 65536, tid);                 // prefetch tW3
    gemm_layer<128>(sb, OFF_ACT, OFF_W1, acc, lane, mwarp, nwarp);
    __syncthreads();
    epi(smem, 1, acc, lane, mwarp, nwarp);
    CP_WAIT(); __syncthreads();

    // ---- L2: t3 -> kept in registers (tk) ----
    zero_acc(tk);
    cp_w(g_wimg + 163840, sb + OFF_W1, 32768, tid);                // prefetch pW1
    gemm_layer<128>(sb, OFF_ACT, OFF_W0, tk, lane, mwarp, nwarp);
    __syncthreads();
    CP_WAIT(); __syncthreads();

    // ---- L3: p1 ----
    zero_acc(acc);
    cp_w(g_wimg + 196608, sb + OFF_W0, 65536, tid);                // prefetch pW2
    gemm_layer<64>(sb, OFF_OBS, OFF_W1, acc, lane, mwarp, nwarp);
    __syncthreads();
    epi(smem, 2, acc, lane, mwarp, nwarp);
    CP_WAIT(); __syncthreads();

    // ---- L4: p2 ----
    zero_acc(acc);
    cp_w(g_wimg + 262144, sb + OFF_W1, 65536, tid);                // prefetch pW3
    gemm_layer<128>(sb, OFF_ACT, OFF_W0, acc, lane, mwarp, nwarp);
    __syncthreads();
    epi(smem, 3, acc, lane, mwarp, nwarp);
    CP_WAIT(); __syncthreads();

    // ---- L5: p3 ----
    zero_acc(acc);
    gemm_layer<128>(sb, OFF_ACT, OFF_W1, acc, lane, mwarp, nwarp);
    __syncthreads();

    // ---- rewards: mean((t3 - p3 + (tb3-pb3))^2) per row ----
    {
        const float* db = reinterpret_cast<const float*>(smem + OFF_BIAS + 4 * 512);
        int g = lane >> 2, tig = lane & 3;
        float rs[8];
        #pragma unroll
        for (int i = 0; i < 8; i++) rs[i] = 0.f;
        #pragma unroll
        for (int mt = 0; mt < 4; mt++)
            #pragma unroll
            for (int nt = 0; nt < 4; nt++) {
                int col = nwarp * 32 + nt * 8 + tig * 2;
                float b0 = db[col], b1 = db[col + 1];
                #pragma unroll
                for (int h = 0; h < 2; h++) {
                    float d0 = tk[mt][nt][h * 2]     - acc[mt][nt][h * 2]     + b0;
                    float d1 = tk[mt][nt][h * 2 + 1] - acc[mt][nt][h * 2 + 1] + b1;
                    rs[mt * 2 + h] = fmaf(d0, d0, fmaf(d1, d1, rs[mt * 2 + h]));
                }
            }
        #pragma unroll
        for (int i = 0; i < 8; i++) {
            rs[i] += __shfl_xor_sync(0xffffffffu, rs[i], 1);
            rs[i] += __shfl_xor_sync(0xffffffffu, rs[i], 2);
        }
        float* part = reinterpret_cast<float*>(smem + OFF_ACT);
        if (tig == 0) {
            #pragma unroll
            for (int i = 0; i < 8; i++) {
                int mt = i >> 1, h = i & 1;
                int row = mwarp * 64 + mt * 16 + g + h * 8;
                part[nwarp * 128 + row] = rs[i];
            }
        }
    }
    __syncthreads();
    if (tid < 128) {
        const float* part = reinterpret_cast<const float*>(smem + OFF_ACT);
        float r = (part[tid] + part[128 + tid] + part[256 + tid] + part[384 + tid]) * (1.0f / 128.0f);
        out[(size_t)tile * 128 + tid] = r;
        double s = (double)r, q = (double)r * (double)r;
        #pragma unroll
        for (int o = 16; o; o >>= 1) {
            s += __shfl_down_sync(0xffffffffu, s, o);
            q += __shfl_down_sync(0xffffffffu, q, o);
        }
        if (lane == 0) {
            reinterpret_cast<double*>(smem + OFF_ACT + 2048)[wid] = s;
            reinterpret_cast<double*>(smem + OFF_ACT + 2048)[4 + wid] = q;
        }
    }
    __syncthreads();
    if (tid == 0) {
        const double* d = reinterpret_cast<const double*>(smem + OFF_ACT + 2048);
        atomicAdd(&g_acc[0], d[0] + d[1] + d[2] + d[3]);
        atomicAdd(&g_acc[1], d[4] + d[5] + d[6] + d[7]);
    }
}

// ---------------------------------------------------------------------------
// Finalize (Chan merge with running stats) + normalize
// ---------------------------------------------------------------------------
__global__ void rnd_finalize(const float* rm, const float* rm2, const float* rc) {
    double n = (double)BATCH_N;
    double sum = g_acc[0], sq = g_acc[1];
    double bmean = sum / n;
    double bm2 = sq - sum * sum / n;
    double c0 = (double)rc[0];
    double nc = c0 + n;
    double delta = bmean - (double)rm[0];
    double nmean = (double)rm[0] + delta * n / nc;
    double nm2 = (double)rm2[0] + bm2 + delta * delta * c0 * n / nc;
    float stdv = (nc > 1.0) ? (float)sqrt(nm2 / (nc - 1.0)) : 1.0f;
    g_stats[0] = (float)nmean;
    g_stats[1] = 1.0f / (stdv + 1e-8f);
}

__global__ void rnd_norm(float* out) {
    float m = g_stats[0], inv = g_stats[1];
    int i = blockIdx.x * blockDim.x + threadIdx.x;
    if (i < BATCH_N) out[i] = (out[i] - m) * inv;
}

// ---------------------------------------------------------------------------
extern "C" void kernel_launch(void* const* d_in, const int* in_sizes, int n_in,
                              void* d_out, int out_size) {
    const float* obs = (const float*)d_in[0];
    const float* rm  = (const float*)d_in[1];
    const float* rm2 = (const float*)d_in[2];
    const float* rc  = (const float*)d_in[3];
    const float* tW1 = (const float*)d_in[4];
    const float* tb1 = (const float*)d_in[5];
    const float* tW2 = (const float*)d_in[6];
    const float* tb2 = (const float*)d_in[7];
    const float* tW3 = (const float*)d_in[8];
    const float* tb3 = (const float*)d_in[9];
    const float* pW1 = (const float*)d_in[10];
    const float* pb1 = (const float*)d_in[11];
    const float* pW2 = (const float*)d_in[12];
    const float* pb2 = (const float*)d_in[13];
    const float* pW3 = (const float*)d_in[14];
    const float* pb3 = (const float*)d_in[15];
    float* out = (float*)d_out;

    cudaFuncSetAttribute(rnd_main, cudaFuncAttributeMaxDynamicSharedMemorySize, SMEM_BYTES);

    rnd_prep<<<dim3(64, 6), 256>>>(tW1, tW2, tW3, pW1, pW2, pW3);
    rnd_main<<<NTILES, 256, SMEM_BYTES>>>(obs, out, tb1, tb2, tb3, pb1, pb2, pb3);
    rnd_finalize<<<1, 1>>>(rm, rm2, rc);
    rnd_norm<<<(BATCH_N + 255) / 256, 256>>>(out);
}